// round 1
// baseline (speedup 1.0000x reference)
#include <cuda_runtime.h>

// Problem constants (fixed shapes for this problem instance)
#define NE 8          // experts
#define TOPK 2
#define HD 1024       // hidden
#define FD 2048       // intermediate
#define NT 8192       // tokens = B*S = 2*4096
#define NSLOT (NT*TOPK)

#define BM 64
#define BN 64
#define BK 16

// ---------------- device scratch (no allocations allowed) ----------------
__device__ int   d_count[NE];
__device__ int   d_offset[NE];
__device__ int   d_etok[NE * NT];        // packed (token*2 + k) per expert slot position
__device__ int   d_slot[NSLOT];          // (token,k) -> compact global slot
__device__ float d_tw[NSLOT];            // (token,k) -> combine weight
__device__ float d_g[(size_t)NSLOT * FD];  // gate*up intermediate, per slot  (134 MB)
__device__ float d_y[(size_t)NSLOT * HD];  // down-proj result, per slot       (67 MB)

// ---------------- helpers ----------------
__global__ void zero_counts_kernel() {
    int i = threadIdx.x;
    if (i < NE) d_count[i] = 0;
}

__global__ void scan_kernel() {
    // single thread prefix sum over 8 counts
    int off = 0;
    for (int e = 0; e < NE; e++) { d_offset[e] = off; off += d_count[e]; }
}

__global__ void remap_kernel() {
    int e = blockIdx.x;
    int n = d_count[e];
    int off = d_offset[e];
    for (int p = threadIdx.x; p < n; p += blockDim.x) {
        int tk = d_etok[e * NT + p];
        d_slot[tk] = off + p;
    }
}

// ---------------- router: logits, softmax, top-2, scatter ----------------
// 256 threads = 8 warps, 1 token per warp.
__global__ __launch_bounds__(256) void router_kernel(
    const float* __restrict__ x, const float* __restrict__ gw,
    float* __restrict__ logits_out)
{
    __shared__ float gws[NE * HD];
    for (int i = threadIdx.x; i < NE * HD; i += blockDim.x) gws[i] = gw[i];
    __syncthreads();

    int warp = threadIdx.x >> 5, lane = threadIdx.x & 31;
    int t = blockIdx.x * 8 + warp;
    if (t >= NT) return;

    const float* xr = x + (size_t)t * HD;
    float acc[NE];
#pragma unroll
    for (int e = 0; e < NE; e++) acc[e] = 0.f;

    for (int h = lane * 4; h < HD; h += 32 * 4) {
        float4 xv = *(const float4*)(xr + h);
#pragma unroll
        for (int e = 0; e < NE; e++) {
            float4 wv = *(const float4*)(&gws[e * HD + h]);
            acc[e] += xv.x * wv.x + xv.y * wv.y + xv.z * wv.z + xv.w * wv.w;
        }
    }
#pragma unroll
    for (int e = 0; e < NE; e++) {
        for (int o = 16; o > 0; o >>= 1)
            acc[e] += __shfl_xor_sync(0xffffffffu, acc[e], o);
    }

    if (lane == 0) {
        if (logits_out) {
#pragma unroll
            for (int e = 0; e < NE; e++) logits_out[(size_t)t * NE + e] = acc[e];
        }
        // softmax (stable)
        float m = acc[0];
#pragma unroll
        for (int e = 1; e < NE; e++) m = fmaxf(m, acc[e]);
        float p[NE];
#pragma unroll
        for (int e = 0; e < NE; e++) p[e] = expf(acc[e] - m);
        // top-2 (lowest index wins ties, matching lax.top_k)
        int i1 = 0;
#pragma unroll
        for (int e = 1; e < NE; e++) if (p[e] > p[i1]) i1 = e;
        int i2 = (i1 == 0) ? 1 : 0;
#pragma unroll
        for (int e = 0; e < NE; e++) if (e != i1 && p[e] > p[i2]) i2 = e;
        float s2 = p[i1] + p[i2];
        d_tw[t * 2 + 0] = p[i1] / s2;
        d_tw[t * 2 + 1] = p[i2] / s2;
        int pos = atomicAdd(&d_count[i1], 1);
        d_etok[i1 * NT + pos] = t * 2 + 0;
        pos = atomicAdd(&d_count[i2], 1);
        d_etok[i2 * NT + pos] = t * 2 + 1;
    }
}

// ---------------- stage A: G = silu(X Wg) * (X Wu), gathered rows ----------------
// grid: (FD/BN, NT/BM, NE); 256 threads, 4x4 microtile, two fused outputs.
__global__ __launch_bounds__(256) void gemm_gu_kernel(
    const float* __restrict__ x,
    const float* __restrict__ Wg, const float* __restrict__ Wu)
{
    int e = blockIdx.z;
    int n = d_count[e];
    int m0 = blockIdx.y * BM;
    if (m0 >= n) return;
    int off = d_offset[e];
    int n0 = blockIdx.x * BN;

    __shared__ float Ast[BK][BM + 1];
    __shared__ float Bg[BK][BN];
    __shared__ float Bu[BK][BN];
    __shared__ int toks[BM];

    int tid = threadIdx.x;
    if (tid < BM) {
        int r = m0 + tid;
        toks[tid] = (r < n) ? (d_etok[e * NT + r] >> 1) : -1;
    }
    __syncthreads();

    int tx = tid & 15, ty = tid >> 4;
    int arow = tid >> 2, akq = tid & 3;
    int brow = tid >> 4, bc = (tid & 15) * 4;
    int tokA = toks[arow];

    const float* wg = Wg + (size_t)e * HD * FD;
    const float* wu = Wu + (size_t)e * HD * FD;

    float cg[4][4], cu[4][4];
#pragma unroll
    for (int i = 0; i < 4; i++)
#pragma unroll
        for (int j = 0; j < 4; j++) { cg[i][j] = 0.f; cu[i][j] = 0.f; }

    for (int k0 = 0; k0 < HD; k0 += BK) {
        float4 av = make_float4(0.f, 0.f, 0.f, 0.f);
        if (tokA >= 0) av = *(const float4*)(x + (size_t)tokA * HD + k0 + akq * 4);
        Ast[akq * 4 + 0][arow] = av.x;
        Ast[akq * 4 + 1][arow] = av.y;
        Ast[akq * 4 + 2][arow] = av.z;
        Ast[akq * 4 + 3][arow] = av.w;
        *(float4*)&Bg[brow][bc] = *(const float4*)(wg + (size_t)(k0 + brow) * FD + n0 + bc);
        *(float4*)&Bu[brow][bc] = *(const float4*)(wu + (size_t)(k0 + brow) * FD + n0 + bc);
        __syncthreads();

#pragma unroll
        for (int kk = 0; kk < BK; kk++) {
            float a[4];
#pragma unroll
            for (int i = 0; i < 4; i++) a[i] = Ast[kk][ty * 4 + i];
            float4 bgv = *(const float4*)&Bg[kk][tx * 4];
            float4 buv = *(const float4*)&Bu[kk][tx * 4];
            float bgs[4] = {bgv.x, bgv.y, bgv.z, bgv.w};
            float bus[4] = {buv.x, buv.y, buv.z, buv.w};
#pragma unroll
            for (int i = 0; i < 4; i++)
#pragma unroll
                for (int j = 0; j < 4; j++) {
                    cg[i][j] = fmaf(a[i], bgs[j], cg[i][j]);
                    cu[i][j] = fmaf(a[i], bus[j], cu[i][j]);
                }
        }
        __syncthreads();
    }

#pragma unroll
    for (int i = 0; i < 4; i++) {
        int r = m0 + ty * 4 + i;
        if (r < n) {
            float4 o;
            float v0 = cg[i][0], v1 = cg[i][1], v2 = cg[i][2], v3 = cg[i][3];
            o.x = (v0 / (1.f + expf(-v0))) * cu[i][0];
            o.y = (v1 / (1.f + expf(-v1))) * cu[i][1];
            o.z = (v2 / (1.f + expf(-v2))) * cu[i][2];
            o.w = (v3 / (1.f + expf(-v3))) * cu[i][3];
            *(float4*)(d_g + (size_t)(off + r) * FD + n0 + tx * 4) = o;
        }
    }
}

// ---------------- stage B: Y = G @ Wd (per slot) ----------------
// grid: (HD/BN, NT/BM, NE)
__global__ __launch_bounds__(256) void gemm_d_kernel(const float* __restrict__ Wd)
{
    int e = blockIdx.z;
    int n = d_count[e];
    int m0 = blockIdx.y * BM;
    if (m0 >= n) return;
    int off = d_offset[e];
    int n0 = blockIdx.x * BN;

    __shared__ float Ast[BK][BM + 1];
    __shared__ float Bs[BK][BN];

    int tid = threadIdx.x;
    int tx = tid & 15, ty = tid >> 4;
    int arow = tid >> 2, akq = tid & 3;
    int brow = tid >> 4, bc = (tid & 15) * 4;

    const float* wd = Wd + (size_t)e * FD * HD;
    bool avalid = (m0 + arow) < n;
    const float* arow_ptr = d_g + (size_t)(off + m0 + arow) * FD;

    float c[4][4];
#pragma unroll
    for (int i = 0; i < 4; i++)
#pragma unroll
        for (int j = 0; j < 4; j++) c[i][j] = 0.f;

    for (int k0 = 0; k0 < FD; k0 += BK) {
        float4 av = make_float4(0.f, 0.f, 0.f, 0.f);
        if (avalid) av = *(const float4*)(arow_ptr + k0 + akq * 4);
        Ast[akq * 4 + 0][arow] = av.x;
        Ast[akq * 4 + 1][arow] = av.y;
        Ast[akq * 4 + 2][arow] = av.z;
        Ast[akq * 4 + 3][arow] = av.w;
        *(float4*)&Bs[brow][bc] = *(const float4*)(wd + (size_t)(k0 + brow) * HD + n0 + bc);
        __syncthreads();

#pragma unroll
        for (int kk = 0; kk < BK; kk++) {
            float a[4];
#pragma unroll
            for (int i = 0; i < 4; i++) a[i] = Ast[kk][ty * 4 + i];
            float4 bv = *(const float4*)&Bs[kk][tx * 4];
            float bs[4] = {bv.x, bv.y, bv.z, bv.w};
#pragma unroll
            for (int i = 0; i < 4; i++)
#pragma unroll
                for (int j = 0; j < 4; j++)
                    c[i][j] = fmaf(a[i], bs[j], c[i][j]);
        }
        __syncthreads();
    }

#pragma unroll
    for (int i = 0; i < 4; i++) {
        int r = m0 + ty * 4 + i;
        if (r < n) {
            float4 o = make_float4(c[i][0], c[i][1], c[i][2], c[i][3]);
            *(float4*)(d_y + (size_t)(off + r) * HD + n0 + tx * 4) = o;
        }
    }
}

// ---------------- combine: out[t] = w0*Y[slot0] + w1*Y[slot1] ----------------
__global__ __launch_bounds__(256) void combine_kernel(float* __restrict__ out)
{
    int t = blockIdx.x;
    int s0 = d_slot[t * 2 + 0];
    int s1 = d_slot[t * 2 + 1];
    float w0 = d_tw[t * 2 + 0];
    float w1 = d_tw[t * 2 + 1];
    const float* y0 = d_y + (size_t)s0 * HD;
    const float* y1 = d_y + (size_t)s1 * HD;
    float* o = out + (size_t)t * HD;
    for (int h = threadIdx.x * 4; h < HD; h += blockDim.x * 4) {
        float4 a = *(const float4*)(y0 + h);
        float4 b = *(const float4*)(y1 + h);
        float4 r;
        r.x = w0 * a.x + w1 * b.x;
        r.y = w0 * a.y + w1 * b.y;
        r.z = w0 * a.z + w1 * b.z;
        r.w = w0 * a.w + w1 * b.w;
        *(float4*)(o + h) = r;
    }
}

// ---------------- launch ----------------
extern "C" void kernel_launch(void* const* d_in, const int* in_sizes, int n_in,
                              void* d_out, int out_size)
{
    const float* x  = (const float*)d_in[0];   // [2,4096,1024]
    const float* gw = (const float*)d_in[1];   // [8,1024]
    const float* Wg = (const float*)d_in[2];   // [8,1024,2048]
    const float* Wu = (const float*)d_in[3];   // [8,1024,2048]
    const float* Wd = (const float*)d_in[4];   // [8,2048,1024]

    float* out = (float*)d_out;

    const int OUT_ELEMS = NT * HD;      // 8388608
    const int LOG_ELEMS = NT * NE;      // 65536

    float* out_main = nullptr;
    float* out_logits = nullptr;
    if (out_size >= OUT_ELEMS + LOG_ELEMS) {
        out_main = out;
        out_logits = out + (size_t)OUT_ELEMS;
    } else if (out_size >= OUT_ELEMS) {
        out_main = out;
    } else {
        out_logits = out;   // degenerate: only logits requested
    }

    zero_counts_kernel<<<1, 32>>>();
    router_kernel<<<NT / 8, 256>>>(x, gw, out_logits);
    scan_kernel<<<1, 1>>>();
    remap_kernel<<<NE, 256>>>();

    if (out_main) {
        dim3 gA(FD / BN, NT / BM, NE);
        gemm_gu_kernel<<<gA, 256>>>(x, Wg, Wu);
        dim3 gB(HD / BN, NT / BM, NE);
        gemm_d_kernel<<<gB, 256>>>(Wd);
        combine_kernel<<<NT, 256>>>(out_main);
    }
}

// round 7
// speedup vs baseline: 1.6225x; 1.6225x over previous
#include <cuda_runtime.h>
#include <cuda_bf16.h>
#include <cstdint>

#define NE 8
#define HD 1024
#define FD 2048
#define NT 8192
#define NSLOT (NT*2)

// ---------------- device scratch (same as proven R1) ----------------
__device__ int   d_count[NE];
__device__ int   d_offset[NE];
__device__ int   d_etok[NE * NT];
__device__ int   d_slot[NSLOT];
__device__ float d_tw[NSLOT];
__device__ float d_g[(size_t)NSLOT * FD];
__device__ float d_y[(size_t)NSLOT * HD];

// ---------------- helpers ----------------
__device__ __forceinline__ void mma16816(float* d, const uint32_t* a, const uint32_t* b) {
    asm volatile("mma.sync.aligned.m16n8k16.row.col.f32.bf16.bf16.f32 "
        "{%0,%1,%2,%3}, {%4,%5,%6,%7}, {%8,%9}, {%0,%1,%2,%3};"
        : "+f"(d[0]), "+f"(d[1]), "+f"(d[2]), "+f"(d[3])
        : "r"(a[0]), "r"(a[1]), "r"(a[2]), "r"(a[3]), "r"(b[0]), "r"(b[1]));
}
__device__ __forceinline__ uint32_t pack2(__nv_bfloat16 a, __nv_bfloat16 b) {
    return (uint32_t)__bfloat16_as_ushort(a) | ((uint32_t)__bfloat16_as_ushort(b) << 16);
}
// split float4 (4 consecutive k) into hi/lo packed uint2
__device__ __forceinline__ void split4(float4 v, uint2& hi, uint2& lo) {
    __nv_bfloat16 h0 = __float2bfloat16(v.x), h1 = __float2bfloat16(v.y);
    __nv_bfloat16 h2 = __float2bfloat16(v.z), h3 = __float2bfloat16(v.w);
    __nv_bfloat16 l0 = __float2bfloat16(v.x - __bfloat162float(h0));
    __nv_bfloat16 l1 = __float2bfloat16(v.y - __bfloat162float(h1));
    __nv_bfloat16 l2 = __float2bfloat16(v.z - __bfloat162float(h2));
    __nv_bfloat16 l3 = __float2bfloat16(v.w - __bfloat162float(h3));
    hi.x = pack2(h0, h1); hi.y = pack2(h2, h3);
    lo.x = pack2(l0, l1); lo.y = pack2(l2, l3);
}

#define ARS 40           // bf16 tile row stride in bytes (16 k * 2B + 8 pad)
#define TILE_BYTES 2560  // 64 rows * 40
#define LOFF TILE_BYTES  // lo tile follows hi tile

// ---------------- routing (byte-identical to R1, proven) ----------------
__global__ void zero_counts_kernel() {
    if (threadIdx.x < NE) d_count[threadIdx.x] = 0;
}
__global__ void scan_kernel() {
    int off = 0;
    for (int e = 0; e < NE; e++) { d_offset[e] = off; off += d_count[e]; }
}
__global__ void remap_kernel() {
    int e = blockIdx.x;
    int n = d_count[e], off = d_offset[e];
    for (int p = threadIdx.x; p < n; p += blockDim.x)
        d_slot[d_etok[e * NT + p]] = off + p;
}

__global__ __launch_bounds__(256) void router_kernel(
    const float* __restrict__ x, const float* __restrict__ gw,
    float* __restrict__ logits_out)
{
    __shared__ float gws[NE * HD];
    for (int i = threadIdx.x; i < NE * HD; i += blockDim.x) gws[i] = gw[i];
    __syncthreads();

    int warp = threadIdx.x >> 5, lane = threadIdx.x & 31;
    int t = blockIdx.x * 8 + warp;
    if (t >= NT) return;

    const float* xr = x + (size_t)t * HD;
    float acc[NE];
#pragma unroll
    for (int e = 0; e < NE; e++) acc[e] = 0.f;
    for (int h = lane * 4; h < HD; h += 128) {
        float4 xv = *(const float4*)(xr + h);
#pragma unroll
        for (int e = 0; e < NE; e++) {
            float4 wv = *(const float4*)(&gws[e * HD + h]);
            acc[e] += xv.x * wv.x + xv.y * wv.y + xv.z * wv.z + xv.w * wv.w;
        }
    }
#pragma unroll
    for (int e = 0; e < NE; e++)
        for (int o = 16; o > 0; o >>= 1)
            acc[e] += __shfl_xor_sync(0xffffffffu, acc[e], o);

    if (lane == 0) {
        if (logits_out) {
#pragma unroll
            for (int e = 0; e < NE; e++) logits_out[(size_t)t * NE + e] = acc[e];
        }
        float m = acc[0];
#pragma unroll
        for (int e = 1; e < NE; e++) m = fmaxf(m, acc[e]);
        float p[NE];
#pragma unroll
        for (int e = 0; e < NE; e++) p[e] = expf(acc[e] - m);
        int i1 = 0;
#pragma unroll
        for (int e = 1; e < NE; e++) if (p[e] > p[i1]) i1 = e;
        int i2 = (i1 == 0) ? 1 : 0;
#pragma unroll
        for (int e = 0; e < NE; e++) if (e != i1 && p[e] > p[i2]) i2 = e;
        float s2 = p[i1] + p[i2];
        d_tw[t * 2 + 0] = p[i1] / s2;
        d_tw[t * 2 + 1] = p[i2] / s2;
        int pos = atomicAdd(&d_count[i1], 1);
        d_etok[i1 * NT + pos] = t * 2 + 0;
        pos = atomicAdd(&d_count[i2], 1);
        d_etok[i2 * NT + pos] = t * 2 + 1;
    }
}

// ---------------- stage A: G = silu(X Wg) * (X Wu), mma.sync, fp32 sources ----------------
// CTA tile 64(m) x 64(n), BK=16. 8 warps: warp tile m16 x n32 (4x2 layout).
// smem: A hi/lo [64][16]bf16 + pad, Bg hi/lo, Bu hi/lo. No ldmatrix, no cp.async.
__global__ __launch_bounds__(256) void gemm_gu_mma(
    const float* __restrict__ x,
    const float* __restrict__ Wg, const float* __restrict__ Wu)
{
    __shared__ __align__(16) char sA[2 * TILE_BYTES];
    __shared__ __align__(16) char sBg[2 * TILE_BYTES];
    __shared__ __align__(16) char sBu[2 * TILE_BYTES];
    __shared__ int toks[64];

    int e = blockIdx.z;
    int n = d_count[e];
    int m0 = blockIdx.y * 64;
    if (m0 >= n) return;
    int off = d_offset[e];
    int n0 = blockIdx.x * 64;
    int rows = min(64, n - m0);

    int tid = threadIdx.x, lane = tid & 31, wid = tid >> 5;
    if (tid < 64) toks[tid] = d_etok[e * NT + m0 + min(tid, rows - 1)] >> 1;
    __syncthreads();

    const float* wg = Wg + (size_t)e * HD * FD;
    const float* wu = Wu + (size_t)e * HD * FD;

    // load assignments
    int arow = tid >> 2, akq = tid & 3;       // A: 64 rows x 4 k-quads
    int bn = tid & 63, bkq = tid >> 6;        // B: 64 n x 4 k-quads

    // fragment lane mapping
    int fr = lane >> 2, fc = lane & 3;
    int wm = (wid & 3) * 16, wn = (wid >> 2) * 32;

    float cg[4][4], cu[4][4];
#pragma unroll
    for (int j = 0; j < 4; j++)
#pragma unroll
        for (int q = 0; q < 4; q++) { cg[j][q] = 0.f; cu[j][q] = 0.f; }

    const int NC = HD / 16;  // 64
    for (int ci = 0; ci < NC; ci++) {
        int k0 = ci * 16;
        // ---- load + split + store ----
        {
            float4 av = *(const float4*)(x + (size_t)toks[arow] * HD + k0 + akq * 4);
            uint2 hi, lo; split4(av, hi, lo);
            *(uint2*)(sA + arow * ARS + akq * 8) = hi;
            *(uint2*)(sA + LOFF + arow * ARS + akq * 8) = lo;

            // B: 4 strided loads along k (rows of W), fixed n -> coalesced across threads
            int kb = k0 + bkq * 4;
            float4 gv, uv;
            gv.x = wg[(size_t)(kb + 0) * FD + n0 + bn];
            gv.y = wg[(size_t)(kb + 1) * FD + n0 + bn];
            gv.z = wg[(size_t)(kb + 2) * FD + n0 + bn];
            gv.w = wg[(size_t)(kb + 3) * FD + n0 + bn];
            uv.x = wu[(size_t)(kb + 0) * FD + n0 + bn];
            uv.y = wu[(size_t)(kb + 1) * FD + n0 + bn];
            uv.z = wu[(size_t)(kb + 2) * FD + n0 + bn];
            uv.w = wu[(size_t)(kb + 3) * FD + n0 + bn];
            split4(gv, hi, lo);
            *(uint2*)(sBg + bn * ARS + bkq * 8) = hi;
            *(uint2*)(sBg + LOFF + bn * ARS + bkq * 8) = lo;
            split4(uv, hi, lo);
            *(uint2*)(sBu + bn * ARS + bkq * 8) = hi;
            *(uint2*)(sBu + LOFF + bn * ARS + bkq * 8) = lo;
        }
        __syncthreads();
        // ---- fragments + mma ----
        {
            uint32_t ah[4], al[4];
            int ab = (wm + fr) * ARS + fc * 4;
            ah[0] = *(const uint32_t*)(sA + ab);
            ah[1] = *(const uint32_t*)(sA + ab + 8 * ARS);
            ah[2] = *(const uint32_t*)(sA + ab + 16);
            ah[3] = *(const uint32_t*)(sA + ab + 8 * ARS + 16);
            al[0] = *(const uint32_t*)(sA + LOFF + ab);
            al[1] = *(const uint32_t*)(sA + LOFF + ab + 8 * ARS);
            al[2] = *(const uint32_t*)(sA + LOFF + ab + 16);
            al[3] = *(const uint32_t*)(sA + LOFF + ab + 8 * ARS + 16);
#pragma unroll
            for (int j = 0; j < 4; j++) {
                int bb = (wn + j * 8 + fr) * ARS + fc * 4;
                uint32_t bh[2], bl[2];
                bh[0] = *(const uint32_t*)(sBg + bb);
                bh[1] = *(const uint32_t*)(sBg + bb + 16);
                bl[0] = *(const uint32_t*)(sBg + LOFF + bb);
                bl[1] = *(const uint32_t*)(sBg + LOFF + bb + 16);
                mma16816(cg[j], ah, bh);
                mma16816(cg[j], al, bh);
                mma16816(cg[j], ah, bl);
                bh[0] = *(const uint32_t*)(sBu + bb);
                bh[1] = *(const uint32_t*)(sBu + bb + 16);
                bl[0] = *(const uint32_t*)(sBu + LOFF + bb);
                bl[1] = *(const uint32_t*)(sBu + LOFF + bb + 16);
                mma16816(cu[j], ah, bh);
                mma16816(cu[j], al, bh);
                mma16816(cu[j], ah, bl);
            }
        }
        __syncthreads();
    }

    // ---- epilogue: silu(g)*u -> d_g fp32 ----
#pragma unroll
    for (int h = 0; h < 2; h++) {
        int row = wm + fr + h * 8;
        if (row < rows) {
            size_t rb = (size_t)(off + m0 + row) * FD + n0 + wn + fc * 2;
#pragma unroll
            for (int j = 0; j < 4; j++) {
                float g0 = cg[j][h * 2 + 0], g1 = cg[j][h * 2 + 1];
                float u0 = cu[j][h * 2 + 0], u1 = cu[j][h * 2 + 1];
                float v0 = g0 / (1.f + expf(-g0)) * u0;
                float v1 = g1 / (1.f + expf(-g1)) * u1;
                *(float2*)(d_g + rb + j * 8) = make_float2(v0, v1);
            }
        }
    }
}

// ---------------- stage B: Y = G @ Wd, mma.sync ----------------
__global__ __launch_bounds__(256) void gemm_d_mma(const float* __restrict__ Wd)
{
    __shared__ __align__(16) char sA[2 * TILE_BYTES];
    __shared__ __align__(16) char sB[2 * TILE_BYTES];

    int e = blockIdx.z;
    int n = d_count[e];
    int m0 = blockIdx.y * 64;
    if (m0 >= n) return;
    int off = d_offset[e];
    int n0 = blockIdx.x * 64;
    int rows = min(64, n - m0);

    int tid = threadIdx.x, lane = tid & 31, wid = tid >> 5;
    const float* wd = Wd + (size_t)e * FD * HD;

    int arow = tid >> 2, akq = tid & 3;
    int bn = tid & 63, bkq = tid >> 6;
    int fr = lane >> 2, fc = lane & 3;
    int wm = (wid & 3) * 16, wn = (wid >> 2) * 32;

    int ar = min(arow, rows - 1);
    const float* asrc = d_g + (size_t)(off + m0 + ar) * FD;

    float cc[4][4];
#pragma unroll
    for (int j = 0; j < 4; j++)
#pragma unroll
        for (int q = 0; q < 4; q++) cc[j][q] = 0.f;

    const int NC = FD / 16;  // 128
    for (int ci = 0; ci < NC; ci++) {
        int k0 = ci * 16;
        {
            float4 av = *(const float4*)(asrc + k0 + akq * 4);
            uint2 hi, lo; split4(av, hi, lo);
            *(uint2*)(sA + arow * ARS + akq * 8) = hi;
            *(uint2*)(sA + LOFF + arow * ARS + akq * 8) = lo;

            int kb = k0 + bkq * 4;
            float4 bv;
            bv.x = wd[(size_t)(kb + 0) * HD + n0 + bn];
            bv.y = wd[(size_t)(kb + 1) * HD + n0 + bn];
            bv.z = wd[(size_t)(kb + 2) * HD + n0 + bn];
            bv.w = wd[(size_t)(kb + 3) * HD + n0 + bn];
            split4(bv, hi, lo);
            *(uint2*)(sB + bn * ARS + bkq * 8) = hi;
            *(uint2*)(sB + LOFF + bn * ARS + bkq * 8) = lo;
        }
        __syncthreads();
        {
            uint32_t ah[4], al[4];
            int ab = (wm + fr) * ARS + fc * 4;
            ah[0] = *(const uint32_t*)(sA + ab);
            ah[1] = *(const uint32_t*)(sA + ab + 8 * ARS);
            ah[2] = *(const uint32_t*)(sA + ab + 16);
            ah[3] = *(const uint32_t*)(sA + ab + 8 * ARS + 16);
            al[0] = *(const uint32_t*)(sA + LOFF + ab);
            al[1] = *(const uint32_t*)(sA + LOFF + ab + 8 * ARS);
            al[2] = *(const uint32_t*)(sA + LOFF + ab + 16);
            al[3] = *(const uint32_t*)(sA + LOFF + ab + 8 * ARS + 16);
#pragma unroll
            for (int j = 0; j < 4; j++) {
                int bb = (wn + j * 8 + fr) * ARS + fc * 4;
                uint32_t bh[2], bl[2];
                bh[0] = *(const uint32_t*)(sB + bb);
                bh[1] = *(const uint32_t*)(sB + bb + 16);
                bl[0] = *(const uint32_t*)(sB + LOFF + bb);
                bl[1] = *(const uint32_t*)(sB + LOFF + bb + 16);
                mma16816(cc[j], ah, bh);
                mma16816(cc[j], al, bh);
                mma16816(cc[j], ah, bl);
            }
        }
        __syncthreads();
    }

#pragma unroll
    for (int h = 0; h < 2; h++) {
        int row = wm + fr + h * 8;
        if (row < rows) {
            size_t rb = (size_t)(off + m0 + row) * HD + n0 + wn + fc * 2;
#pragma unroll
            for (int j = 0; j < 4; j++)
                *(float2*)(d_y + rb + j * 8) = make_float2(cc[j][h * 2 + 0], cc[j][h * 2 + 1]);
        }
    }
}

// ---------------- combine (byte-identical to R1, proven) ----------------
__global__ __launch_bounds__(256) void combine_kernel(float* __restrict__ out)
{
    int t = blockIdx.x;
    int s0 = d_slot[t * 2 + 0], s1 = d_slot[t * 2 + 1];
    float w0 = d_tw[t * 2 + 0], w1 = d_tw[t * 2 + 1];
    const float* y0 = d_y + (size_t)s0 * HD;
    const float* y1 = d_y + (size_t)s1 * HD;
    float* o = out + (size_t)t * HD;
    for (int h = threadIdx.x * 4; h < HD; h += blockDim.x * 4) {
        float4 a = *(const float4*)(y0 + h);
        float4 b = *(const float4*)(y1 + h);
        *(float4*)(o + h) = make_float4(w0 * a.x + w1 * b.x, w0 * a.y + w1 * b.y,
                                        w0 * a.z + w1 * b.z, w0 * a.w + w1 * b.w);
    }
}

// ---------------- launch ----------------
extern "C" void kernel_launch(void* const* d_in, const int* in_sizes, int n_in,
                              void* d_out, int out_size)
{
    const float* x  = (const float*)d_in[0];
    const float* gw = (const float*)d_in[1];
    const float* Wg = (const float*)d_in[2];
    const float* Wu = (const float*)d_in[3];
    const float* Wd = (const float*)d_in[4];

    float* out = (float*)d_out;
    const int OUT_ELEMS = NT * HD;
    const int LOG_ELEMS = NT * NE;

    float* out_main = nullptr;
    float* out_logits = nullptr;
    if (out_size >= OUT_ELEMS + LOG_ELEMS) { out_main = out; out_logits = out + (size_t)OUT_ELEMS; }
    else if (out_size >= OUT_ELEMS)        { out_main = out; }
    else                                   { out_logits = out; }

    zero_counts_kernel<<<1, 32>>>();
    router_kernel<<<NT / 8, 256>>>(x, gw, out_logits);
    scan_kernel<<<1, 1>>>();
    remap_kernel<<<NE, 256>>>();

    if (out_main) {
        gemm_gu_mma<<<dim3(FD / 64, NT / 64, NE), 256>>>(x, Wg, Wu);
        gemm_d_mma<<<dim3(HD / 64, NT / 64, NE), 256>>>(Wd);
        combine_kernel<<<NT, 256>>>(out_main);
    }
}